// round 6
// baseline (speedup 1.0000x reference)
#include <cuda_runtime.h>
#include <cuda_bf16.h>

// Problem shapes (fixed by the dataset)
#define WW    256
#define HW    (256 * 256)   // 65536
#define TOTAL (128 * 256)   // 32768

#define NBLK  64
#define NTHR  512           // 64 * 512 = 32768 threads, 1 element each

// Per-thread / per-warp 32-bit pack: bits [0,24) = loss*2^16 sum (max 32*2^16=2^21),
// bits [24,32) = count (max 32).
// Global 64-bit pack: bits [0,36) = sum(loss*2^16) (max 2^31),
// bits [36,52) = count (max 32768), bits [56,64) = block arrivals (64).
__device__ unsigned long long g_acc = 0ULL;

#define Q_SCALE   65536.0f               // 2^16
#define WCNT_ONE  (1u << 24)
#define GCNT_SH   36
#define BLK_ONE   (1ULL << 56)
#define GSUM_MASK ((1ULL << 36) - 1)

__global__ __launch_bounds__(NTHR) void iou_loss_fused(
    const float* __restrict__ out,      // [B, 2, H, W]
    const float* __restrict__ target,   // [B, N, 2]
    const int*   __restrict__ ind,      // [B, N]
    const int*   __restrict__ mask,     // [B, N] (bool promoted to int32)
    float*       __restrict__ d_out)
{
    const int t   = threadIdx.x;
    const int idx = blockIdx.x * NTHR + t;    // 0..32767
    const int b   = idx >> 8;                 // element / 256 = batch

    // front-batched independent loads
    const int    mk = mask[idx];
    const int    id = ind[idx];
    const float2 tg = reinterpret_cast<const float2*>(target)[idx];

    unsigned int val = 0u;

    if (mk != 0) {
        const float* base = out + (unsigned)b * (2 * HW);
        const float dx = __ldg(base + id);        // channel 0
        const float dy = __ldg(base + HW + id);   // channel 1

        const float tx = tg.x, ty = tg.y;
        const float x  = (float)(id & (WW - 1));
        const float y  = (float)(id >> 8);

        // trunc toward zero, matching torch .int() / jnp.trunc
        const float gx = truncf(x - tx * 0.5f);
        const float gy = truncf(y - ty * 0.5f);
        const float px = truncf(x - dx * 0.5f);
        const float py = truncf(y - dy * 0.5f);

        const float g_x1 = gx - tx * 0.5f, g_x2 = gx + tx * 0.5f;
        const float g_y1 = gy - ty * 0.5f, g_y2 = gy + ty * 0.5f;
        const float d_x1 = px - dx * 0.5f, d_x2 = px + dx * 0.5f;
        const float d_y1 = py - dy * 0.5f, d_y2 = py + dy * 0.5f;

        const float iw = fmaxf(fminf(g_x2, d_x2) - fmaxf(g_x1, d_x1), 0.0f);
        const float ih = fmaxf(fminf(g_y2, d_y2) - fmaxf(g_y1, d_y1), 0.0f);
        const float inter = iw * ih;

        const float w1 = g_x2 - g_x1, h1 = g_y2 - g_y1;
        const float w2 = d_x2 - d_x1, h2 = d_y2 - d_y1;
        const float uni = w1 * h1 + 1e-16f + w2 * h2 - inter;

        // loss in [0,1]; clamp against ulp overshoot before unsigned cast
        const float loss = fmaxf(1.0f - inter / uni, 0.0f);
        val = (unsigned int)(loss * Q_SCALE) + WCNT_ONE;
    }

    // ── 32-bit warp reduction (exact integer, single-register shfl) ──
    #pragma unroll
    for (int off = 16; off > 0; off >>= 1)
        val += __shfl_down_sync(0xFFFFFFFFu, val, off);

    __shared__ unsigned int s_val[NTHR / 32];   // 16 warps
    const int lane = t & 31, warp = t >> 5;
    if (lane == 0) s_val[warp] = val;
    __syncthreads();

    // warp 0 reduces the 16 per-warp partials in parallel, widening to 64-bit
    if (warp == 0) {
        unsigned int w32 = (lane < NTHR / 32) ? s_val[lane] : 0u;
        // split into (sum, cnt) and widen so 16-way sum can't overflow fields
        unsigned long long v = (unsigned long long)(w32 & 0xFFFFFF)
                             + ((unsigned long long)(w32 >> 24) << GCNT_SH);
        #pragma unroll
        for (int off = 8; off > 0; off >>= 1)
            v += __shfl_down_sync(0xFFFFFFFFu, v, off);

        if (lane == 0) {
            v += BLK_ONE;   // this block's arrival mark
            const unsigned long long total = atomicAdd(&g_acc, v) + v;

            if ((unsigned)(total >> 56) == NBLK) {
                // atomic total order: we hold the complete sum — finalize
                const float sumf = (float)(total & GSUM_MASK) * (1.0f / Q_SCALE);
                const float cnt  = (float)(unsigned)((total >> GCNT_SH) & 0xFFFF);
                d_out[0] = sumf / (4.0f * cnt + 0.0001f);
                g_acc = 0ULL;             // reset for next graph replay
            }
        }
    }
}

extern "C" void kernel_launch(void* const* d_in, const int* in_sizes, int n_in,
                              void* d_out, int out_size)
{
    const float* out_map = (const float*)d_in[0];  // [128,2,256,256] f32
    const float* target  = (const float*)d_in[1];  // [128,256,2]     f32
    const int*   ind     = (const int*)  d_in[2];  // [128,256]       i32
    const int*   mask    = (const int*)  d_in[3];  // [128,256]       i32 (bool)
    float*       outp    = (float*)d_out;

    iou_loss_fused<<<NBLK, NTHR>>>(out_map, target, ind, mask, outp);
}

// round 7
// speedup vs baseline: 1.0186x; 1.0186x over previous
#include <cuda_runtime.h>
#include <cuda_bf16.h>

// Problem shapes (fixed by the dataset)
#define BB   128            // batch = grid (one wave on 148 SMs)
#define NN   256            // boxes per batch = block
#define WW   256
#define HW   (256 * 256)    // 65536

// Per-warp 32-bit pack: bits [0,24) = sum(loss*2^16) (max 32*2^16 = 2^21),
// bits [24,32) = count (max 32). REDUX.SUM-safe.
// Global 64-bit pack: bits [0,36) = sum(loss*2^16) (max 32768*2^16 = 2^31),
// bits [36,52) = count (max 32768), bits [56,64) = block arrivals (128).
__device__ unsigned long long g_acc = 0ULL;

#define Q_SCALE   65536.0f               // 2^16
#define WCNT_ONE  (1u << 24)
#define GCNT_SH   36
#define BLK_ONE   (1ULL << 56)
#define GSUM_MASK ((1ULL << 36) - 1)

__global__ __launch_bounds__(NN) void iou_loss_fused(
    const float* __restrict__ out,      // [B, 2, H, W]
    const float* __restrict__ target,   // [B, N, 2]
    const int*   __restrict__ ind,      // [B, N]
    const int*   __restrict__ mask,     // [B, N] (bool promoted to int32)
    float*       __restrict__ d_out)
{
    const int b   = blockIdx.x;
    const int n   = threadIdx.x;
    const int idx = b * NN + n;

    // front-batched independent loads
    const int    mk = mask[idx];
    const int    id = ind[idx];
    const float2 tg = reinterpret_cast<const float2*>(target)[idx];

    unsigned int val = 0u;

    if (mk != 0) {
        const float* base = out + (unsigned)b * (2 * HW);
        const float dx = __ldg(base + id);        // channel 0
        const float dy = __ldg(base + HW + id);   // channel 1

        const float tx = tg.x, ty = tg.y;
        const float x  = (float)(id & (WW - 1));
        const float y  = (float)(id >> 8);

        // trunc toward zero, matching torch .int() / jnp.trunc
        const float gx = truncf(x - tx * 0.5f);
        const float gy = truncf(y - ty * 0.5f);
        const float px = truncf(x - dx * 0.5f);
        const float py = truncf(y - dy * 0.5f);

        const float g_x1 = gx - tx * 0.5f, g_x2 = gx + tx * 0.5f;
        const float g_y1 = gy - ty * 0.5f, g_y2 = gy + ty * 0.5f;
        const float d_x1 = px - dx * 0.5f, d_x2 = px + dx * 0.5f;
        const float d_y1 = py - dy * 0.5f, d_y2 = py + dy * 0.5f;

        const float iw = fmaxf(fminf(g_x2, d_x2) - fmaxf(g_x1, d_x1), 0.0f);
        const float ih = fmaxf(fminf(g_y2, d_y2) - fmaxf(g_y1, d_y1), 0.0f);
        const float inter = iw * ih;

        const float w1 = g_x2 - g_x1, h1 = g_y2 - g_y1;
        const float w2 = d_x2 - d_x1, h2 = d_y2 - d_y1;
        const float uni = w1 * h1 + 1e-16f + w2 * h2 - inter;

        // loss in [0,1]; clamp against ulp overshoot before unsigned cast
        const float loss = fmaxf(1.0f - inter / uni, 0.0f);
        val = (unsigned int)(loss * Q_SCALE) + WCNT_ONE;
    }

    // ── single-instruction warp reduction (REDUX.SUM) ──
    const unsigned int wsum = __reduce_add_sync(0xFFFFFFFFu, val);

    __shared__ unsigned int s_val[NN / 32];   // 8 warps
    const int lane = n & 31, warp = n >> 5;
    if (lane == 0) s_val[warp] = wsum;
    __syncthreads();

    // warp 0: widen the 8 partials and reduce in parallel (3 shfl steps)
    if (warp == 0) {
        unsigned int w32 = (lane < NN / 32) ? s_val[lane] : 0u;
        unsigned long long v = (unsigned long long)(w32 & 0xFFFFFF)
                             + ((unsigned long long)(w32 >> 24) << GCNT_SH);
        #pragma unroll
        for (int off = 4; off > 0; off >>= 1)
            v += __shfl_down_sync(0xFFFFFFFFu, v, off);

        if (lane == 0) {
            v += BLK_ONE;   // this block's arrival mark
            const unsigned long long total = atomicAdd(&g_acc, v) + v;

            if ((unsigned)(total >> 56) == BB) {
                // atomic total order: we hold the complete sum — finalize
                const float sumf = (float)(total & GSUM_MASK) * (1.0f / Q_SCALE);
                const float cnt  = (float)(unsigned)((total >> GCNT_SH) & 0xFFFF);
                d_out[0] = sumf / (4.0f * cnt + 0.0001f);
                g_acc = 0ULL;             // reset for next graph replay
            }
        }
    }
}

extern "C" void kernel_launch(void* const* d_in, const int* in_sizes, int n_in,
                              void* d_out, int out_size)
{
    const float* out_map = (const float*)d_in[0];  // [128,2,256,256] f32
    const float* target  = (const float*)d_in[1];  // [128,256,2]     f32
    const int*   ind     = (const int*)  d_in[2];  // [128,256]       i32
    const int*   mask    = (const int*)  d_in[3];  // [128,256]       i32 (bool)
    float*       outp    = (float*)d_out;

    iou_loss_fused<<<BB, NN>>>(out_map, target, ind, mask, outp);
}

// round 8
// speedup vs baseline: 1.0529x; 1.0337x over previous
#include <cuda_runtime.h>
#include <cuda_bf16.h>

// Problem shapes (fixed by the dataset)
#define WW    256
#define HW    (256 * 256)   // 65536

#define NBLK  64
#define NTHR  256
#define VPT   2             // 64 * 256 * 2 = 32768 elements

// Per-warp 32-bit pack: bits [0,24) = sum(loss*2^16) (max 64*2^16 = 2^22),
// bits [24,32) = count (max 64). REDUX.SUM-safe.
// Global 64-bit pack: bits [0,36) = sum(loss*2^16) (max 32768*2^16 = 2^31),
// bits [36,52) = count (max 32768), bits [56,64) = block arrivals (64).
__device__ unsigned long long g_acc = 0ULL;

#define Q_SCALE   65536.0f               // 2^16
#define WCNT_ONE  (1u << 24)
#define GCNT_SH   36
#define BLK_ONE   (1ULL << 56)
#define GSUM_MASK ((1ULL << 36) - 1)

__global__ __launch_bounds__(NTHR) void iou_loss_fused(
    const float* __restrict__ out,      // [B, 2, H, W]
    const float* __restrict__ target,   // [B, N, 2]
    const int*   __restrict__ ind,      // [B, N]
    const int*   __restrict__ mask,     // [B, N] (bool promoted to int32)
    float*       __restrict__ d_out)
{
    const int t   = threadIdx.x;
    const int vid = blockIdx.x * NTHR + t;    // 0..16383
    // element pair: idx0 = 2*vid, idx0+1. batch = element >> 8.

    // ── front-batched independent wide loads (MLP overlaps DRAM latency) ──
    const int2   mk2 = reinterpret_cast<const int2*>(mask)[vid];
    const int2   id2 = reinterpret_cast<const int2*>(ind)[vid];
    const float4 tg4 = reinterpret_cast<const float4*>(target)[vid];

    // both elements share the same batch? element0 = 2*vid, element1 = 2*vid+1:
    // batch changes only every 256 elements and 2*vid,2*vid+1 straddle a
    // boundary never (256 even), so b is identical for the pair.
    const int b = vid >> 7;                   // (2*vid) >> 8
    const float* base = out + (unsigned)b * (2 * HW);

    // front-batch gathers: issue all four unconditionally-addressed loads,
    // predicated only by mask (compiler keeps them independent LDGs).
    float dx0 = 0.f, dy0 = 0.f, dx1 = 0.f, dy1 = 0.f;
    if (mk2.x != 0) { dx0 = __ldg(base + id2.x); dy0 = __ldg(base + HW + id2.x); }
    if (mk2.y != 0) { dx1 = __ldg(base + id2.y); dy1 = __ldg(base + HW + id2.y); }

    unsigned int val = 0u;

    #pragma unroll
    for (int i = 0; i < VPT; i++) {
        const int   mk = i ? mk2.y : mk2.x;
        if (mk == 0) continue;
        const int   id = i ? id2.y : id2.x;
        const float tx = i ? tg4.z : tg4.x;
        const float ty = i ? tg4.w : tg4.y;
        const float dx = i ? dx1 : dx0;
        const float dy = i ? dy1 : dy0;

        const float x  = (float)(id & (WW - 1));
        const float y  = (float)(id >> 8);

        // trunc toward zero, matching torch .int() / jnp.trunc
        const float gx = truncf(x - tx * 0.5f);
        const float gy = truncf(y - ty * 0.5f);
        const float px = truncf(x - dx * 0.5f);
        const float py = truncf(y - dy * 0.5f);

        const float g_x1 = gx - tx * 0.5f, g_x2 = gx + tx * 0.5f;
        const float g_y1 = gy - ty * 0.5f, g_y2 = gy + ty * 0.5f;
        const float d_x1 = px - dx * 0.5f, d_x2 = px + dx * 0.5f;
        const float d_y1 = py - dy * 0.5f, d_y2 = py + dy * 0.5f;

        const float iw = fmaxf(fminf(g_x2, d_x2) - fmaxf(g_x1, d_x1), 0.0f);
        const float ih = fmaxf(fminf(g_y2, d_y2) - fmaxf(g_y1, d_y1), 0.0f);
        const float inter = iw * ih;

        const float w1 = g_x2 - g_x1, h1 = g_y2 - g_y1;
        const float w2 = d_x2 - d_x1, h2 = d_y2 - d_y1;
        const float uni = w1 * h1 + 1e-16f + w2 * h2 - inter;

        const float loss = fmaxf(1.0f - inter / uni, 0.0f);   // in [0,1]
        val += (unsigned int)(loss * Q_SCALE) + WCNT_ONE;
    }

    // ── single-instruction warp reduction (REDUX.SUM) ──
    const unsigned int wsum = __reduce_add_sync(0xFFFFFFFFu, val);

    __shared__ unsigned int s_val[NTHR / 32];   // 8 warps
    const int lane = t & 31, warp = t >> 5;
    if (lane == 0) s_val[warp] = wsum;
    __syncthreads();

    // warp 0: widen the 8 partials and reduce in parallel (3 shfl steps)
    if (warp == 0) {
        unsigned int w32 = (lane < NTHR / 32) ? s_val[lane] : 0u;
        unsigned long long v = (unsigned long long)(w32 & 0xFFFFFF)
                             + ((unsigned long long)(w32 >> 24) << GCNT_SH);
        #pragma unroll
        for (int off = 4; off > 0; off >>= 1)
            v += __shfl_down_sync(0xFFFFFFFFu, v, off);

        if (lane == 0) {
            v += BLK_ONE;   // this block's arrival mark
            const unsigned long long total = atomicAdd(&g_acc, v) + v;

            if ((unsigned)(total >> 56) == NBLK) {
                // atomic total order: we hold the complete sum — finalize
                const float sumf = (float)(total & GSUM_MASK) * (1.0f / Q_SCALE);
                const float cnt  = (float)(unsigned)((total >> GCNT_SH) & 0xFFFF);
                d_out[0] = sumf / (4.0f * cnt + 0.0001f);
                g_acc = 0ULL;             // reset for next graph replay
            }
        }
    }
}

extern "C" void kernel_launch(void* const* d_in, const int* in_sizes, int n_in,
                              void* d_out, int out_size)
{
    const float* out_map = (const float*)d_in[0];  // [128,2,256,256] f32
    const float* target  = (const float*)d_in[1];  // [128,256,2]     f32
    const int*   ind     = (const int*)  d_in[2];  // [128,256]       i32
    const int*   mask    = (const int*)  d_in[3];  // [128,256]       i32 (bool)
    float*       outp    = (float*)d_out;

    iou_loss_fused<<<NBLK, NTHR>>>(out_map, target, ind, mask, outp);
}